// round 7
// baseline (speedup 1.0000x reference)
#include <cuda_runtime.h>
#include <cstdint>

#define NFFT 512
#define THREADS 64
#define CHUNK 8      /* rows per block, cp.async-pipelined (32768 % 8 == 0) */
#define PADDED 576   /* 512 + 512/8 : padding keeps transpose phases conflict-light */

struct cplx { float re, im; };

__device__ __forceinline__ cplx cadd(cplx a, cplx b) { return {a.re + b.re, a.im + b.im}; }
__device__ __forceinline__ cplx csub(cplx a, cplx b) { return {a.re - b.re, a.im - b.im}; }
__device__ __forceinline__ cplx cmul(cplx a, cplx b) {
    return {fmaf(a.re, b.re, -a.im * b.im), fmaf(a.re, b.im, a.im * b.re)};
}
// multiply by -i : (x + iy)*(-i) = y - ix
__device__ __forceinline__ cplx mul_mi(cplx a) { return {a.im, -a.re}; }

// Forward DFT-8: b[k] = sum_r a[r] * exp(-2*pi*i*r*k/8)
__device__ __forceinline__ void dft8(const cplx* a, cplx* b) {
    const float S = 0.70710678118654752440f;
    cplx e0 = cadd(a[0], a[4]), e1 = csub(a[0], a[4]);
    cplx e2 = cadd(a[2], a[6]), e3 = csub(a[2], a[6]);
    cplx E0 = cadd(e0, e2), E2 = csub(e0, e2);
    cplx m3 = mul_mi(e3);
    cplx E1 = cadd(e1, m3), E3 = csub(e1, m3);
    cplx o0 = cadd(a[1], a[5]), o1 = csub(a[1], a[5]);
    cplx o2 = cadd(a[3], a[7]), o3 = csub(a[3], a[7]);
    cplx O0 = cadd(o0, o2), O2 = csub(o0, o2);
    cplx n3 = mul_mi(o3);
    cplx O1 = cadd(o1, n3), O3 = csub(o1, n3);
    cplx O1w = { S * (O1.re + O1.im), S * (O1.im - O1.re) };
    cplx O2w = mul_mi(O2);
    cplx O3w = { S * (O3.im - O3.re), -S * (O3.re + O3.im) };
    b[0] = cadd(E0, O0);  b[4] = csub(E0, O0);
    b[1] = cadd(E1, O1w); b[5] = csub(E1, O1w);
    b[2] = cadd(E2, O2w); b[6] = csub(E2, O2w);
    b[3] = cadd(E3, O3w); b[7] = csub(E3, O3w);
}

__device__ __forceinline__ int pad(int idx) { return idx + (idx >> 3); }

// twiddle powers t^1..t^7 with shallow dependency tree (depth 3)
__device__ __forceinline__ void tw_powers(cplx t1, cplx* t) {
    t[1] = t1;
    t[2] = cmul(t1, t1);
    t[3] = cmul(t[2], t1);
    t[4] = cmul(t[2], t[2]);
    t[5] = cmul(t[2], t[3]);
    t[6] = cmul(t[3], t[3]);
    t[7] = cmul(t[3], t[4]);
}

__device__ __forceinline__ void cp16(uint32_t smem_dst, const float* gsrc) {
    asm volatile("cp.async.cg.shared.global [%0], [%1], 16;"
                 :: "r"(smem_dst), "l"(gsrc) : "memory");
}

__global__ __launch_bounds__(THREADS)
void range_fft512_kernel(const float* __restrict__ xre,
                         const float* __restrict__ xim,
                         float2* __restrict__ out,
                         int nrows)
{
    __shared__ float stg_re[2][NFFT];
    __shared__ float stg_im[2][NFFT];
    __shared__ float2 bufA[PADDED];
    __shared__ float2 bufB[PADDED];

    const int lane = threadIdx.x;          // 0..63
    const long long base = (long long)blockIdx.x * CHUNK;

    const float TWO_PI_OVER_N = 6.28318530717958647692f / (float)NFFT;

    // row-invariant twiddle bases (hoisted)
    float s0, c0, s1b, c1b;
    __sincosf(-TWO_PI_OVER_N * (float)lane, &s0, &c0);                 // stage-0 base, p = lane
    __sincosf(-TWO_PI_OVER_N * (float)(8 * (lane >> 3)), &s1b, &c1b);  // stage-1 base, p = lane>>3

    // async row loader: 4x16B per thread (re: 2 chunks, im: 2 chunks), one commit group per row
    auto issue_row = [&](int slot, long long row) {
        long long r = row < nrows ? row : 0;
        const float* xr = xre + r * NFFT + lane * 4;
        const float* xi = xim + r * NFFT + lane * 4;
        uint32_t dre = (uint32_t)__cvta_generic_to_shared(&stg_re[slot][lane * 4]);
        uint32_t dim = (uint32_t)__cvta_generic_to_shared(&stg_im[slot][lane * 4]);
        cp16(dre,        xr);
        cp16(dre + 1024, xr + 256);
        cp16(dim,        xi);
        cp16(dim + 1024, xi + 256);
        asm volatile("cp.async.commit_group;" ::: "memory");
    };

    // prologue: depth-2 prefetch
    issue_row(0, base);
    issue_row(1, base + 1);

    #pragma unroll
    for (int rr = 0; rr < CHUNK; rr++) {
        const long long row = base + rr;
        const bool valid = row < nrows;
        const int s = rr & 1;

        // wait for this row's staging buffer (keep <=1 younger group in flight)
        if (rr + 1 < CHUNK) asm volatile("cp.async.wait_group 1;" ::: "memory");
        else                asm volatile("cp.async.wait_group 0;" ::: "memory");
        __syncthreads();   // all threads' chunks visible

        // ---- stage 0: n=512, s=1. p = lane. stg -> bufA ----
        {
            cplx a[8], b[8];
            #pragma unroll
            for (int r = 0; r < 8; r++) {
                a[r].re = stg_re[s][lane + 64 * r];   // stride-1 across lanes: conflict-free
                a[r].im = stg_im[s][lane + 64 * r];
            }
            dft8(a, b);
            const int p = lane;
            cplx t[8];
            tw_powers(cplx{c0, s0}, t);
            bufA[pad(8 * p + 0)] = make_float2(b[0].re, b[0].im);
            #pragma unroll
            for (int k = 1; k < 8; k++) {
                cplx c = cmul(b[k], t[k]);
                bufA[pad(8 * p + k)] = make_float2(c.re, c.im);
            }
        }
        __syncthreads();   // bufA ready; stg[s] fully consumed by all threads

        // refill the freed staging buffer while stages 1-2 compute
        if (rr + 2 < CHUNK) issue_row(s, base + rr + 2);

        // ---- stage 1: n=64, s=8. p = lane>>3, q = lane&7. bufA -> bufB ----
        {
            const int p = lane >> 3, q = lane & 7;
            cplx a[8], b[8];
            #pragma unroll
            for (int r = 0; r < 8; r++) {
                float2 v = bufA[pad(lane + 64 * r)];   // q + 8p == lane
                a[r] = {v.x, v.y};
            }
            dft8(a, b);
            cplx t[8];
            tw_powers(cplx{c1b, s1b}, t);
            bufB[pad(q + 64 * p + 0)] = make_float2(b[0].re, b[0].im);
            #pragma unroll
            for (int k = 1; k < 8; k++) {
                cplx c = cmul(b[k], t[k]);
                bufB[pad(q + 64 * p + 8 * k)] = make_float2(c.re, c.im);
            }
        }
        __syncthreads();   // bufB ready; bufA free for next row

        // ---- stage 2: n=8, s=64. twiddle==1. bufB -> gmem ----
        {
            cplx a[8], b[8];
            #pragma unroll
            for (int r = 0; r < 8; r++) {
                float2 v = bufB[pad(lane + 64 * r)];
                a[r] = {v.x, v.y};
            }
            dft8(a, b);
            if (valid) {
                float2* o = out + row * NFFT;      // interleaved (re, im)
                #pragma unroll
                for (int k = 0; k < 8; k++)
                    __stcs(o + lane + 64 * k, make_float2(b[k].re, b[k].im));
            }
        }
        // no barrier here: bufB isn't rewritten until after next row's bufA barrier
    }
}

extern "C" void kernel_launch(void* const* d_in, const int* in_sizes, int n_in,
                              void* d_out, int out_size) {
    const float* xre = (const float*)d_in[0];
    const float* xim = (const float*)d_in[1];
    (void)n_in; (void)out_size;

    int nrows = in_sizes[0] / NFFT;   // 8*16*256 = 32768
    int grid  = (nrows + CHUNK - 1) / CHUNK;
    range_fft512_kernel<<<grid, THREADS>>>(xre, xim, (float2*)d_out, nrows);
}

// round 8
// speedup vs baseline: 1.2979x; 1.2979x over previous
#include <cuda_runtime.h>

#define NFFT 512
#define THREADS 64
#define CHUNK 8      /* rows per block, register-pipelined (32768 % 8 == 0) */
#define PADDED 576   /* 512 + 512/8 : padding keeps transpose phases conflict-light */

struct cplx { float re, im; };

__device__ __forceinline__ cplx cadd(cplx a, cplx b) { return {a.re + b.re, a.im + b.im}; }
__device__ __forceinline__ cplx csub(cplx a, cplx b) { return {a.re - b.re, a.im - b.im}; }
__device__ __forceinline__ cplx cmul(cplx a, cplx b) {
    return {fmaf(a.re, b.re, -a.im * b.im), fmaf(a.re, b.im, a.im * b.re)};
}
// multiply by -i : (x + iy)*(-i) = y - ix
__device__ __forceinline__ cplx mul_mi(cplx a) { return {a.im, -a.re}; }

// Forward DFT-8: b[k] = sum_r a[r] * exp(-2*pi*i*r*k/8)
__device__ __forceinline__ void dft8(const cplx* a, cplx* b) {
    const float S = 0.70710678118654752440f;
    cplx e0 = cadd(a[0], a[4]), e1 = csub(a[0], a[4]);
    cplx e2 = cadd(a[2], a[6]), e3 = csub(a[2], a[6]);
    cplx E0 = cadd(e0, e2), E2 = csub(e0, e2);
    cplx m3 = mul_mi(e3);
    cplx E1 = cadd(e1, m3), E3 = csub(e1, m3);
    cplx o0 = cadd(a[1], a[5]), o1 = csub(a[1], a[5]);
    cplx o2 = cadd(a[3], a[7]), o3 = csub(a[3], a[7]);
    cplx O0 = cadd(o0, o2), O2 = csub(o0, o2);
    cplx n3 = mul_mi(o3);
    cplx O1 = cadd(o1, n3), O3 = csub(o1, n3);
    cplx O1w = { S * (O1.re + O1.im), S * (O1.im - O1.re) };
    cplx O2w = mul_mi(O2);
    cplx O3w = { S * (O3.im - O3.re), -S * (O3.re + O3.im) };
    b[0] = cadd(E0, O0);  b[4] = csub(E0, O0);
    b[1] = cadd(E1, O1w); b[5] = csub(E1, O1w);
    b[2] = cadd(E2, O2w); b[6] = csub(E2, O2w);
    b[3] = cadd(E3, O3w); b[7] = csub(E3, O3w);
}

__device__ __forceinline__ int pad(int idx) { return idx + (idx >> 3); }

__global__ __launch_bounds__(THREADS, 12)
void range_fft512_kernel(const float* __restrict__ xre,
                         const float* __restrict__ xim,
                         float2* __restrict__ out,
                         int nrows)
{
    __shared__ float2 bufA[PADDED];
    __shared__ float2 bufB[PADDED];

    const int lane = threadIdx.x;          // 0..63
    const long long base = (long long)blockIdx.x * CHUNK;

    const float TWO_PI_OVER_N = 6.28318530717958647692f / (float)NFFT;

    // row-invariant twiddle bases (hoisted)
    float s0, c0, s1b, c1b;
    __sincosf(-TWO_PI_OVER_N * (float)lane, &s0, &c0);                 // stage-0 base, p = lane
    __sincosf(-TWO_PI_OVER_N * (float)(8 * (lane >> 3)), &s1b, &c1b);  // stage-1 base, p = lane>>3

    // prologue: load row 0 into registers
    float cr[8], ci[8];
    {
        long long r0 = base < nrows ? base : 0;
        const float* xr = xre + r0 * NFFT;
        const float* xi = xim + r0 * NFFT;
        #pragma unroll
        for (int r = 0; r < 8; r++) {
            cr[r] = __ldcs(xr + lane + 64 * r);
            ci[r] = __ldcs(xi + lane + 64 * r);
        }
    }

    #pragma unroll
    for (int rr = 0; rr < CHUNK; rr++) {
        const long long row = base + rr;
        const bool valid = row < nrows;

        // ---- stage 0: n=512, s=1. p = lane. regs -> bufA ----
        {
            cplx a[8], b[8];
            #pragma unroll
            for (int r = 0; r < 8; r++) a[r] = {cr[r], ci[r]};
            dft8(a, b);
            const int p = lane;
            cplx t1 = {c0, s0}, t = t1;          // running twiddle: 4 live regs
            bufA[pad(8 * p + 0)] = make_float2(b[0].re, b[0].im);
            #pragma unroll
            for (int k = 1; k < 8; k++) {
                cplx c = cmul(b[k], t);
                bufA[pad(8 * p + k)] = make_float2(c.re, c.im);
                if (k < 7) t = cmul(t, t1);
            }
        }

        // prefetch next row (issued after stage-0 writes; latency hidden by
        // barrier + stages 1-2; adds zero smem traffic)
        float nr[8], ni[8];
        if (rr + 1 < CHUNK) {
            long long nrow = (base + rr + 1) < nrows ? (base + rr + 1) : 0;
            const float* xr = xre + nrow * NFFT;
            const float* xi = xim + nrow * NFFT;
            #pragma unroll
            for (int r = 0; r < 8; r++) {
                nr[r] = __ldcs(xr + lane + 64 * r);
                ni[r] = __ldcs(xi + lane + 64 * r);
            }
        }

        __syncthreads();   // bufA ready

        // ---- stage 1: n=64, s=8. p = lane>>3, q = lane&7. bufA -> bufB ----
        {
            const int p = lane >> 3, q = lane & 7;
            cplx a[8], b[8];
            #pragma unroll
            for (int r = 0; r < 8; r++) {
                float2 v = bufA[pad(lane + 64 * r)];   // q + 8p == lane
                a[r] = {v.x, v.y};
            }
            dft8(a, b);
            cplx t1 = {c1b, s1b}, t = t1;
            bufB[pad(q + 64 * p + 0)] = make_float2(b[0].re, b[0].im);
            #pragma unroll
            for (int k = 1; k < 8; k++) {
                cplx c = cmul(b[k], t);
                bufB[pad(q + 64 * p + 8 * k)] = make_float2(c.re, c.im);
                if (k < 7) t = cmul(t, t1);
            }
        }
        __syncthreads();   // bufB ready; bufA free for next row

        // ---- stage 2: n=8, s=64. twiddle==1. bufB -> gmem ----
        {
            cplx a[8], b[8];
            #pragma unroll
            for (int r = 0; r < 8; r++) {
                float2 v = bufB[pad(lane + 64 * r)];
                a[r] = {v.x, v.y};
            }
            dft8(a, b);
            if (valid) {
                float2* o = out + row * NFFT;      // interleaved (re, im)
                #pragma unroll
                for (int k = 0; k < 8; k++)
                    __stcs(o + lane + 64 * k, make_float2(b[k].re, b[k].im));
            }
        }
        // no barrier here: bufB isn't rewritten until after next row's bufA barrier

        // rotate prefetch into current
        if (rr + 1 < CHUNK) {
            #pragma unroll
            for (int r = 0; r < 8; r++) { cr[r] = nr[r]; ci[r] = ni[r]; }
        }
    }
}

extern "C" void kernel_launch(void* const* d_in, const int* in_sizes, int n_in,
                              void* d_out, int out_size) {
    const float* xre = (const float*)d_in[0];
    const float* xim = (const float*)d_in[1];
    (void)n_in; (void)out_size;

    int nrows = in_sizes[0] / NFFT;   // 8*16*256 = 32768
    int grid  = (nrows + CHUNK - 1) / CHUNK;
    range_fft512_kernel<<<grid, THREADS>>>(xre, xim, (float2*)d_out, nrows);
}

// round 10
// speedup vs baseline: 1.3046x; 1.0052x over previous
#include <cuda_runtime.h>

#define NFFT 512
#define THREADS 64
#define PAIRS 4      /* row-pairs per block = 8 rows (32768 % 8 == 0) */
#define PADDED 576   /* 512 + 512/8 : padding keeps transpose phases conflict-light */

struct cplx { float re, im; };

__device__ __forceinline__ cplx cadd(cplx a, cplx b) { return {a.re + b.re, a.im + b.im}; }
__device__ __forceinline__ cplx csub(cplx a, cplx b) { return {a.re - b.re, a.im - b.im}; }
__device__ __forceinline__ cplx cmul(cplx a, cplx b) {
    return {fmaf(a.re, b.re, -a.im * b.im), fmaf(a.re, b.im, a.im * b.re)};
}
// multiply by -i : (x + iy)*(-i) = y - ix
__device__ __forceinline__ cplx mul_mi(cplx a) { return {a.im, -a.re}; }

// Forward DFT-8: b[k] = sum_r a[r] * exp(-2*pi*i*r*k/8)
__device__ __forceinline__ void dft8(const cplx* a, cplx* b) {
    const float S = 0.70710678118654752440f;
    cplx e0 = cadd(a[0], a[4]), e1 = csub(a[0], a[4]);
    cplx e2 = cadd(a[2], a[6]), e3 = csub(a[2], a[6]);
    cplx E0 = cadd(e0, e2), E2 = csub(e0, e2);
    cplx m3 = mul_mi(e3);
    cplx E1 = cadd(e1, m3), E3 = csub(e1, m3);
    cplx o0 = cadd(a[1], a[5]), o1 = csub(a[1], a[5]);
    cplx o2 = cadd(a[3], a[7]), o3 = csub(a[3], a[7]);
    cplx O0 = cadd(o0, o2), O2 = csub(o0, o2);
    cplx n3 = mul_mi(o3);
    cplx O1 = cadd(o1, n3), O3 = csub(o1, n3);
    cplx O1w = { S * (O1.re + O1.im), S * (O1.im - O1.re) };
    cplx O2w = mul_mi(O2);
    cplx O3w = { S * (O3.im - O3.re), -S * (O3.re + O3.im) };
    b[0] = cadd(E0, O0);  b[4] = csub(E0, O0);
    b[1] = cadd(E1, O1w); b[5] = csub(E1, O1w);
    b[2] = cadd(E2, O2w); b[6] = csub(E2, O2w);
    b[3] = cadd(E3, O3w); b[7] = csub(E3, O3w);
}

__device__ __forceinline__ int pad(int idx) { return idx + (idx >> 3); }

// ---- per-row stage helpers ----

__device__ __forceinline__ void stage0_row(const float* cr, const float* ci,
                                           float2* bufA, int lane, cplx t1) {
    cplx a[8], b[8];
    #pragma unroll
    for (int r = 0; r < 8; r++) a[r] = {cr[r], ci[r]};
    dft8(a, b);
    cplx t = t1;                               // running twiddle
    bufA[pad(8 * lane + 0)] = make_float2(b[0].re, b[0].im);
    #pragma unroll
    for (int k = 1; k < 8; k++) {
        cplx c = cmul(b[k], t);
        bufA[pad(8 * lane + k)] = make_float2(c.re, c.im);
        if (k < 7) t = cmul(t, t1);
    }
}

__device__ __forceinline__ void stage1_row(const float2* bufA, float2* bufB,
                                           int lane, cplx t1) {
    const int p = lane >> 3, q = lane & 7;
    cplx a[8], b[8];
    #pragma unroll
    for (int r = 0; r < 8; r++) {
        float2 v = bufA[pad(lane + 64 * r)];   // q + 8p == lane
        a[r] = {v.x, v.y};
    }
    dft8(a, b);
    cplx t = t1;
    bufB[pad(q + 64 * p + 0)] = make_float2(b[0].re, b[0].im);
    #pragma unroll
    for (int k = 1; k < 8; k++) {
        cplx c = cmul(b[k], t);
        bufB[pad(q + 64 * p + 8 * k)] = make_float2(c.re, c.im);
        if (k < 7) t = cmul(t, t1);
    }
}

__device__ __forceinline__ void stage2_row(const float2* bufB, float2* o,
                                           int lane, bool valid) {
    cplx a[8], b[8];
    #pragma unroll
    for (int r = 0; r < 8; r++) {
        float2 v = bufB[pad(lane + 64 * r)];
        a[r] = {v.x, v.y};
    }
    dft8(a, b);
    if (valid) {
        #pragma unroll
        for (int k = 0; k < 8; k++)
            __stcs(o + lane + 64 * k, make_float2(b[k].re, b[k].im));
    }
}

__global__ __launch_bounds__(THREADS)
void range_fft512_kernel(const float* __restrict__ xre,
                         const float* __restrict__ xim,
                         float2* __restrict__ out,
                         int nrows)
{
    __shared__ float2 bufA[2][PADDED];
    __shared__ float2 bufB[2][PADDED];

    const int lane = threadIdx.x;              // 0..63
    const int base = blockIdx.x * (2 * PAIRS); // fits in int: nrows = 32768

    const float TWO_PI_OVER_N = 6.28318530717958647692f / (float)NFFT;

    // row-invariant twiddle bases (hoisted)
    float s0, c0, s1b, c1b;
    __sincosf(-TWO_PI_OVER_N * (float)lane, &s0, &c0);                 // stage-0 base
    __sincosf(-TWO_PI_OVER_N * (float)(8 * (lane >> 3)), &s1b, &c1b);  // stage-1 base

    auto load_row = [&](int row, float* dr, float* di) {
        int r = row < nrows ? row : 0;
        const float* xr = xre + r * NFFT;
        const float* xi = xim + r * NFFT;
        #pragma unroll
        for (int j = 0; j < 8; j++) {
            dr[j] = __ldcs(xr + lane + 64 * j);
            di[j] = __ldcs(xi + lane + 64 * j);
        }
    };

    // prologue: load pair 0
    float cr[2][8], ci[2][8];
    load_row(base + 0, cr[0], ci[0]);
    load_row(base + 1, cr[1], ci[1]);

    #pragma unroll
    for (int rr = 0; rr < PAIRS; rr++) {
        const int r0 = base + 2 * rr;
        const int r1 = r0 + 1;

        // ---- stage 0 for both rows (independent chains, interleavable) ----
        stage0_row(cr[0], ci[0], bufA[0], lane, cplx{c0, s0});
        stage0_row(cr[1], ci[1], bufA[1], lane, cplx{c0, s0});

        // prefetch next pair while stages 1-2 run (zero smem traffic)
        float nr[2][8], ni[2][8];
        if (rr + 1 < PAIRS) {
            load_row(r0 + 2, nr[0], ni[0]);
            load_row(r0 + 3, nr[1], ni[1]);
        }

        __syncthreads();   // bufA[0..1] ready (also: prev iter's bufB reads done)

        // ---- stage 1 for both rows ----
        stage1_row(bufA[0], bufB[0], lane, cplx{c1b, s1b});
        stage1_row(bufA[1], bufB[1], lane, cplx{c1b, s1b});

        __syncthreads();   // bufB[0..1] ready; bufA free for next pair

        // ---- stage 2 + coalesced interleaved (re,im) stores ----
        stage2_row(bufB[0], out + (size_t)r0 * NFFT, lane, r0 < nrows);
        stage2_row(bufB[1], out + (size_t)r1 * NFFT, lane, r1 < nrows);
        // no barrier: bufB not rewritten until after next iter's first barrier

        if (rr + 1 < PAIRS) {
            #pragma unroll
            for (int j = 0; j < 8; j++) {
                cr[0][j] = nr[0][j]; ci[0][j] = ni[0][j];
                cr[1][j] = nr[1][j]; ci[1][j] = ni[1][j];
            }
        }
    }
}

extern "C" void kernel_launch(void* const* d_in, const int* in_sizes, int n_in,
                              void* d_out, int out_size) {
    const float* xre = (const float*)d_in[0];
    const float* xim = (const float*)d_in[1];
    (void)n_in; (void)out_size;

    int nrows = in_sizes[0] / NFFT;              // 8*16*256 = 32768
    int rows_per_blk = 2 * PAIRS;
    int grid = (nrows + rows_per_blk - 1) / rows_per_blk;
    range_fft512_kernel<<<grid, THREADS>>>(xre, xim, (float2*)d_out, nrows);
}